// round 6
// baseline (speedup 1.0000x reference)
#include <cuda_runtime.h>
#include <cuda_bf16.h>
#include <cstdint>

// PCEN, 10 smoother coefficients.
//   m[s,t] = (1-s)*m[s,t-1] + s*x[t],  m[s,0] = x[0]
//   out = (x*(EPS+m)^(-alpha) + delta)^r - delta^r
//
// R6: latency-bound per R5 post-mortem (issue rose, time flat). Max TLP:
// 1 chain per warp (10 warps per (b,f) row, 20480 warps), register state
// halved, __launch_bounds__(128,12) forces <=42 regs -> 75% occupancy.
// Scan: thread-serial float4 x warp Kogge-Stone; 3 MUFU + 1 poly-ex2 per elem.

#define PCEN_EPS 1e-5f
#define NS 10
#define TT 2048
#define RPT 4
#define CHUNK (32 * RPT)
#define NCHUNK (TT / CHUNK)

__device__ __forceinline__ float fast_ex2(float v) {
    float r; asm("ex2.approx.ftz.f32 %0, %1;" : "=f"(r) : "f"(v)); return r;
}
__device__ __forceinline__ float fast_lg2(float v) {
    float r; asm("lg2.approx.ftz.f32 %0, %1;" : "=f"(r) : "f"(v)); return r;
}

// 2^v on FMA/ALU pipes (no MUFU). Valid for |v| < ~126.
__device__ __forceinline__ float poly_ex2(float v) {
    const float magic = 12582912.0f;           // 1.5 * 2^23
    float fl = v + magic;                      // RN -> integer in low mantissa
    int   iv = __float_as_int(fl);
    float t  = v - (fl - magic);               // t in [-0.5, 0.5]
    float u  = t * 0.6931471805599453f;
    float p  = fmaf(u, 8.3333333e-3f, 4.1666667e-2f);
    p = fmaf(p, u, 0.16666667f);
    p = fmaf(p, u, 0.5f);
    p = fmaf(p, u, 1.0f);
    p = fmaf(p, u, 1.0f);
    return __int_as_float(__float_as_int(p) + (iv << 23));
}

__global__ __launch_bounds__(128, 12) void pcen_kernel(
    const float* __restrict__ x,
    const float* __restrict__ s_log,
    const float* __restrict__ alpha_log,
    const float* __restrict__ delta_log,
    const float* __restrict__ r_log,
    float* __restrict__ out,
    int F, int BF)
{
    const int gwarp = (blockIdx.x * blockDim.x + threadIdx.x) >> 5;
    const int lane  = threadIdx.x & 31;
    if (gwarp >= BF * NS) return;

    const int row   = gwarp / NS;   // adjacent warps share a row -> x L1/L2 hot
    const int chain = gwarp % NS;

    const int b = row / F;
    const int f = row % F;

    const float alpha = __expf(alpha_log[f]);
    const float delta = __expf(delta_log[f]);
    const float r     = __expf(r_log[f]);
    const float delta_r = fast_ex2(r * fast_lg2(delta));

    const float4* __restrict__ xp4 = (const float4*)(x + (size_t)row * TT);
    float* __restrict__ op = out + (((size_t)b * NS + chain) * F + f) * (size_t)TT;

    const float s = __expf(s_log[chain]);
    const float a1  = 1.0f - s;
    const float a2  = a1 * a1;
    const float a3  = a2 * a1;
    const float a4  = a2 * a2;
    const float a8  = a4 * a4;
    const float a16 = a8 * a8;
    const float a32 = a16 * a16;
    const float a64 = a32 * a32;
    const float a128 = a64 * a64;
    float a4lane = 1.0f;                       // (a^4)^lane
    if (lane & 1)  a4lane *= a4;
    if (lane & 2)  a4lane *= a8;
    if (lane & 4)  a4lane *= a16;
    if (lane & 8)  a4lane *= a32;
    if (lane & 16) a4lane *= a64;

    // m_{-1} := x0 gives m_0 = (1-s)*x0 + s*x0 = x0 (reference init)
    float carry = ((const float*)xp4)[0];

    for (int ch = 0; ch < NCHUNK; ch++) {
        const float4 xv = xp4[ch * 32 + lane];

        // local serial IIR with zero initial condition
        const float l0 = s * xv.x;
        const float l1 = fmaf(a1, l0, s * xv.y);
        const float l2 = fmaf(a1, l1, s * xv.z);
        const float l3 = fmaf(a1, l2, s * xv.w);

        // Kogge-Stone inclusive scan of lane aggregates (ratio a^4)
        float S = l3;
        float v;
        v = __shfl_up_sync(0xFFFFFFFFu, S, 1);  if (lane >= 1)  S = fmaf(a4,  v, S);
        v = __shfl_up_sync(0xFFFFFFFFu, S, 2);  if (lane >= 2)  S = fmaf(a8,  v, S);
        v = __shfl_up_sync(0xFFFFFFFFu, S, 4);  if (lane >= 4)  S = fmaf(a16, v, S);
        v = __shfl_up_sync(0xFFFFFFFFu, S, 8);  if (lane >= 8)  S = fmaf(a32, v, S);
        v = __shfl_up_sync(0xFFFFFFFFu, S, 16); if (lane >= 16) S = fmaf(a64, v, S);

        // M_prev: final m just before this lane's segment
        const float P = __shfl_up_sync(0xFFFFFFFFu, S, 1);
        const float Mprev = (lane == 0) ? carry : fmaf(a4lane, carry, P);
        const float S31 = __shfl_sync(0xFFFFFFFFu, S, 31);
        carry = fmaf(a128, carry, S31);

        // fold prefix: m_j = l_j + a^{j+1} * Mprev
        const float m0 = fmaf(a1, Mprev, l0);
        const float m1 = fmaf(a2, Mprev, l1);
        const float m2 = fmaf(a3, Mprev, l2);
        const float m3 = fmaf(a4, Mprev, l3);

        float4 o;
        {
            const float sm = fast_ex2(-alpha * fast_lg2(PCEN_EPS + m0));
            o.x = poly_ex2(r * fast_lg2(fmaf(xv.x, sm, delta))) - delta_r;
        }
        {
            const float sm = fast_ex2(-alpha * fast_lg2(PCEN_EPS + m1));
            o.y = poly_ex2(r * fast_lg2(fmaf(xv.y, sm, delta))) - delta_r;
        }
        {
            const float sm = fast_ex2(-alpha * fast_lg2(PCEN_EPS + m2));
            o.z = poly_ex2(r * fast_lg2(fmaf(xv.z, sm, delta))) - delta_r;
        }
        {
            const float sm = fast_ex2(-alpha * fast_lg2(PCEN_EPS + m3));
            o.w = poly_ex2(r * fast_lg2(fmaf(xv.w, sm, delta))) - delta_r;
        }
        *(float4*)(op + (size_t)ch * CHUNK + lane * RPT) = o;
    }
}

extern "C" void kernel_launch(void* const* d_in, const int* in_sizes, int n_in,
                              void* d_out, int out_size)
{
    const float* x         = (const float*)d_in[0];
    const float* s_log     = (const float*)d_in[1];
    const float* alpha_log = (const float*)d_in[2];
    const float* delta_log = (const float*)d_in[3];
    const float* r_log     = (const float*)d_in[4];
    float* out = (float*)d_out;

    const int F  = in_sizes[2];
    const int BF = in_sizes[0] / TT;

    const int total_warps = BF * NS;
    const int threads = 128;
    const int warps_per_block = threads / 32;
    const int blocks = (total_warps + warps_per_block - 1) / warps_per_block;

    pcen_kernel<<<blocks, threads>>>(x, s_log, alpha_log, delta_log, r_log,
                                     out, F, BF);
}